// round 1
// baseline (speedup 1.0000x reference)
#include <cuda_runtime.h>
#include <math.h>

#define NB 2
#define SEQ 2048
#define HID 2048
#define NHQ 16
#define NHKV 8
#define HD 128
#define WIN 1024
#define MROWS (NB*SEQ)   // 4096

// ---------------- scratch (static device globals; no cudaMalloc allowed) ----
__device__ float g_q[(size_t)MROWS * NHQ * HD];     // 33.5 MB
__device__ float g_k[(size_t)MROWS * NHKV * HD];    // 16.8 MB
__device__ float g_v[(size_t)MROWS * NHKV * HD];    // 16.8 MB
__device__ float g_attn[(size_t)MROWS * NHQ * HD];  // 33.5 MB

// ---------------------------------------------------------------------------
// SGEMM (NT): C[M,N] = A[M,K] @ W[N,K]^T.  BM=BN=128, BK=16, 256 thr, 8x8/thr.
// M%128==0, N%128==0, K%16==0 for all call sites.
// ---------------------------------------------------------------------------
__global__ __launch_bounds__(256) void sgemm_nt(
    const float* __restrict__ A, const float* __restrict__ Wt,
    float* __restrict__ C, int M, int N, int K)
{
    __shared__ float As[16][128];
    __shared__ float Bs[16][128];
    const int tid = threadIdx.x;
    const int tx = tid & 15;
    const int ty = tid >> 4;
    const int m0 = blockIdx.y << 7;
    const int n0 = blockIdx.x << 7;
    const int lr = tid >> 1;          // 0..127
    const int lc = (tid & 1) << 3;    // 0 or 8
    const float* Ag = A  + (size_t)(m0 + lr) * K + lc;
    const float* Wg = Wt + (size_t)(n0 + lr) * K + lc;
    float acc[8][8] = {};
    for (int k0 = 0; k0 < K; k0 += 16) {
        float4 a0 = *(const float4*)(Ag + k0);
        float4 a1 = *(const float4*)(Ag + k0 + 4);
        float4 b0 = *(const float4*)(Wg + k0);
        float4 b1 = *(const float4*)(Wg + k0 + 4);
        __syncthreads();
        As[lc+0][lr]=a0.x; As[lc+1][lr]=a0.y; As[lc+2][lr]=a0.z; As[lc+3][lr]=a0.w;
        As[lc+4][lr]=a1.x; As[lc+5][lr]=a1.y; As[lc+6][lr]=a1.z; As[lc+7][lr]=a1.w;
        Bs[lc+0][lr]=b0.x; Bs[lc+1][lr]=b0.y; Bs[lc+2][lr]=b0.z; Bs[lc+3][lr]=b0.w;
        Bs[lc+4][lr]=b1.x; Bs[lc+5][lr]=b1.y; Bs[lc+6][lr]=b1.z; Bs[lc+7][lr]=b1.w;
        __syncthreads();
        #pragma unroll
        for (int kk = 0; kk < 16; kk++) {
            float ra[8], rb[8];
            *(float4*)(ra)   = *(const float4*)&As[kk][ty<<3];
            *(float4*)(ra+4) = *(const float4*)&As[kk][(ty<<3)+4];
            *(float4*)(rb)   = *(const float4*)&Bs[kk][tx<<3];
            *(float4*)(rb+4) = *(const float4*)&Bs[kk][(tx<<3)+4];
            #pragma unroll
            for (int i = 0; i < 8; i++)
                #pragma unroll
                for (int j = 0; j < 8; j++)
                    acc[i][j] = fmaf(ra[i], rb[j], acc[i][j]);
        }
    }
    #pragma unroll
    for (int i = 0; i < 8; i++) {
        float* Cp = C + (size_t)(m0 + (ty<<3) + i) * N + n0 + (tx<<3);
        *(float4*)Cp     = make_float4(acc[i][0], acc[i][1], acc[i][2], acc[i][3]);
        *(float4*)(Cp+4) = make_float4(acc[i][4], acc[i][5], acc[i][6], acc[i][7]);
    }
}

// ---------------------------------------------------------------------------
// Gemma RMSNorm (x * rsqrt(mean(x^2)+eps) * (1+w)) + RoPE, one warp per
// (row, head). Lane owns dims {l, l+32, l+64, l+96}; rope pairs (d, d+64).
// ---------------------------------------------------------------------------
__global__ __launch_bounds__(256) void norm_rope(
    float* __restrict__ x, const float* __restrict__ w, int n_heads)
{
    int gw   = (blockIdx.x * 256 + threadIdx.x) >> 5;
    int lane = threadIdx.x & 31;
    if (gw >= MROWS * n_heads) return;
    int m = gw / n_heads;
    int h = gw - m * n_heads;
    int pos = m & (SEQ - 1);
    float* row = x + (size_t)m * (n_heads * HD) + h * HD;
    float x0 = row[lane], x1 = row[lane+32], x2 = row[lane+64], x3 = row[lane+96];
    float ss = x0*x0 + x1*x1 + x2*x2 + x3*x3;
    #pragma unroll
    for (int o = 16; o; o >>= 1) ss += __shfl_xor_sync(0xffffffffu, ss, o);
    float rstd = rsqrtf(ss * (1.0f / HD) + 1e-6f);
    float y0 = x0 * rstd * (1.f + w[lane]);
    float y1 = x1 * rstd * (1.f + w[lane+32]);
    float y2 = x2 * rstd * (1.f + w[lane+64]);
    float y3 = x3 * rstd * (1.f + w[lane+96]);
    // inv_freq[j] = theta^(-j/64); emb[d] = pos*inv_freq[d mod 64]
    double a0 = (double)pos * pow(10000.0, -(double)lane / 64.0);
    double a1 = (double)pos * pow(10000.0, -(double)(lane + 32) / 64.0);
    double s0d, c0d, s1d, c1d;
    sincos(a0, &s0d, &c0d);
    sincos(a1, &s1d, &c1d);
    float c0 = (float)c0d, s0 = (float)s0d, c1 = (float)c1d, s1 = (float)s1d;
    row[lane]      = y0 * c0 - y2 * s0;   // d<64:  x*cos - x[d+64]*sin
    row[lane+64]   = y2 * c0 + y0 * s0;   // d>=64: x*cos + x[d-64]*sin
    row[lane+32]   = y1 * c1 - y3 * s1;
    row[lane+96]   = y3 * c1 + y1 * s1;
}

// ---------------------------------------------------------------------------
// Flash attention, sliding-window causal, GQA (q head h -> kv head h/2).
// BQ=64 queries x BKT=64 keys per iteration, 256 threads.
// smem: Qs[64][129], KsT[128][65] (d-major), Vs[64][128], Ss[64][65], stats.
// ---------------------------------------------------------------------------
#define BQ 64
#define BKT 64
#define FLASH_SMEM_FLOATS (64*129 + 128*65 + 64*128 + 64*65 + 3*64)
#define FLASH_SMEM_BYTES  (FLASH_SMEM_FLOATS * 4)

__global__ __launch_bounds__(256) void flash_fwd(
    const float* __restrict__ q, const float* __restrict__ k,
    const float* __restrict__ v, float* __restrict__ o)
{
    extern __shared__ float smem[];
    float* Qs  = smem;                 // [64][129]
    float* KsT = Qs  + 64 * 129;       // [128][65]
    float* Vs  = KsT + 128 * 65;       // [64][128]
    float* Ss  = Vs  + 64 * 128;       // [64][65]
    float* m_s = Ss  + 64 * 65;
    float* l_s = m_s + 64;
    float* c_s = l_s + 64;

    const int tid = threadIdx.x;
    const int q0  = blockIdx.x * BQ;
    const int h   = blockIdx.y;
    const int b   = blockIdx.z;
    const int hk  = h >> 1;                     // repeat_interleave(groups=2)
    const float* qbase = q + (size_t)b * SEQ * (NHQ  * HD) + h  * HD;
    const float* kbase = k + (size_t)b * SEQ * (NHKV * HD) + hk * HD;
    const float* vbase = v + (size_t)b * SEQ * (NHKV * HD) + hk * HD;

    // load Q tile (q0..q0+63) -> Qs (stride 129)
    #pragma unroll
    for (int rep = 0; rep < 8; rep++) {
        int idx = rep * 256 + tid;          // float4 index 0..2047
        int r   = idx >> 5;
        int dc  = (idx & 31) << 2;
        float4 va = *(const float4*)(qbase + (size_t)(q0 + r) * (NHQ * HD) + dc);
        float* dst = Qs + r * 129 + dc;
        dst[0] = va.x; dst[1] = va.y; dst[2] = va.z; dst[3] = va.w;
    }
    if (tid < 64) { m_s[tid] = -1e30f; l_s[tid] = 0.f; }

    float acc[8][4] = {};                  // O accumulator
    const int pv_r0 = (tid >> 5) << 3;     // 8 rows per thread
    const int pv_d0 = (tid & 31) << 2;     // 4 dims per thread
    const int qk_r0 = (tid >> 4) << 2;     // 4x4 score block
    const int qk_c0 = (tid & 15) << 2;
    const int sm_r  = tid >> 2;            // 4 threads per row
    const int sm_g  = tid & 3;

    int jlo = q0 - (WIN - 1); if (jlo < 0) jlo = 0;
    const int jstart = jlo & ~(BKT - 1);
    const float scale = 0.08838834764831845f;   // 1/sqrt(128)

    for (int j0 = jstart; j0 <= q0 + BQ - 1; j0 += BKT) {
        __syncthreads();   // protect smem from previous iteration's readers
        // ---- load K (d-major transpose) and V ----
        #pragma unroll
        for (int sub = 0; sub < 8; sub++) {
            int r = tid >> 2;
            int c = (tid & 3) << 2;
            float4 kv = *(const float4*)(kbase + (size_t)(j0 + r) * (NHKV * HD) + sub * 16 + c);
            int dbase = sub * 16 + c;
            KsT[(dbase+0)*65 + r] = kv.x;
            KsT[(dbase+1)*65 + r] = kv.y;
            KsT[(dbase+2)*65 + r] = kv.z;
            KsT[(dbase+3)*65 + r] = kv.w;
        }
        #pragma unroll
        for (int rep = 0; rep < 8; rep++) {
            int idx = rep * 256 + tid;
            int r   = idx >> 5;
            int dc  = (idx & 31) << 2;
            *(float4*)(Vs + r * 128 + dc) =
                *(const float4*)(vbase + (size_t)(j0 + r) * (NHKV * HD) + dc);
        }
        __syncthreads();
        // ---- S = scale * Q K^T with sliding-window mask ----
        {
            float aq[4][4] = {};
            #pragma unroll 8
            for (int kk = 0; kk < 128; kk++) {
                float ra[4], rb[4];
                #pragma unroll
                for (int i = 0; i < 4; i++) ra[i] = Qs[(qk_r0 + i) * 129 + kk];
                #pragma unroll
                for (int j = 0; j < 4; j++) rb[j] = KsT[kk * 65 + qk_c0 + j];
                #pragma unroll
                for (int i = 0; i < 4; i++)
                    #pragma unroll
                    for (int j = 0; j < 4; j++)
                        aq[i][j] = fmaf(ra[i], rb[j], aq[i][j]);
            }
            #pragma unroll
            for (int i = 0; i < 4; i++) {
                int qi = q0 + qk_r0 + i;
                #pragma unroll
                for (int j = 0; j < 4; j++) {
                    int kj = j0 + qk_c0 + j;
                    bool valid = (kj <= qi) && (kj > qi - WIN);
                    Ss[(qk_r0 + i) * 65 + qk_c0 + j] = valid ? aq[i][j] * scale : -1e30f;
                }
            }
        }
        __syncthreads();
        // ---- online softmax (4 threads / row) ----
        {
            float mx = -1e30f;
            #pragma unroll
            for (int u = 0; u < 16; u++) mx = fmaxf(mx, Ss[sm_r * 65 + sm_g * 16 + u]);
            mx = fmaxf(mx, __shfl_xor_sync(0xffffffffu, mx, 1));
            mx = fmaxf(mx, __shfl_xor_sync(0xffffffffu, mx, 2));
            float m_old = m_s[sm_r];
            float m_new = fmaxf(m_old, mx);
            float corr  = __expf(m_old - m_new);
            float psum  = 0.f;
            #pragma unroll
            for (int u = 0; u < 16; u++) {
                float s = Ss[sm_r * 65 + sm_g * 16 + u];
                float p = (s > -1e29f) ? __expf(s - m_new) : 0.f;   // masked -> 0
                Ss[sm_r * 65 + sm_g * 16 + u] = p;
                psum += p;
            }
            psum += __shfl_xor_sync(0xffffffffu, psum, 1);
            psum += __shfl_xor_sync(0xffffffffu, psum, 2);
            if (sm_g == 0) {
                m_s[sm_r] = m_new;
                c_s[sm_r] = corr;
                l_s[sm_r] = l_s[sm_r] * corr + psum;
            }
        }
        __syncthreads();
        // ---- O = O*corr + P V ----
        {
            #pragma unroll
            for (int i = 0; i < 8; i++) {
                float corr = c_s[pv_r0 + i];
                #pragma unroll
                for (int u = 0; u < 4; u++) acc[i][u] *= corr;
            }
            #pragma unroll 4
            for (int j = 0; j < BKT; j++) {
                float4 vv = *(const float4*)(Vs + j * 128 + pv_d0);
                #pragma unroll
                for (int i = 0; i < 8; i++) {
                    float p = Ss[(pv_r0 + i) * 65 + j];
                    acc[i][0] = fmaf(p, vv.x, acc[i][0]);
                    acc[i][1] = fmaf(p, vv.y, acc[i][1]);
                    acc[i][2] = fmaf(p, vv.z, acc[i][2]);
                    acc[i][3] = fmaf(p, vv.w, acc[i][3]);
                }
            }
        }
    }
    // ---- write O / l ----
    float* obase = o + (size_t)b * SEQ * (NHQ * HD) + h * HD;
    #pragma unroll
    for (int i = 0; i < 8; i++) {
        float inv = 1.0f / l_s[pv_r0 + i];
        *(float4*)(obase + (size_t)(q0 + pv_r0 + i) * (NHQ * HD) + pv_d0) =
            make_float4(acc[i][0]*inv, acc[i][1]*inv, acc[i][2]*inv, acc[i][3]*inv);
    }
}

// ---------------------------------------------------------------------------
extern "C" void kernel_launch(void* const* d_in, const int* in_sizes, int n_in,
                              void* d_out, int out_size)
{
    const float* hidden = (const float*)d_in[0];
    const float* wq = (const float*)d_in[1];
    const float* wk = (const float*)d_in[2];
    const float* wv = (const float*)d_in[3];
    const float* wo = (const float*)d_in[4];
    const float* qw = (const float*)d_in[5];
    const float* kw = (const float*)d_in[6];
    float* out = (float*)d_out;

    float *q, *k, *v, *attn;
    cudaGetSymbolAddress((void**)&q,    g_q);
    cudaGetSymbolAddress((void**)&k,    g_k);
    cudaGetSymbolAddress((void**)&v,    g_v);
    cudaGetSymbolAddress((void**)&attn, g_attn);

    cudaFuncSetAttribute(flash_fwd, cudaFuncAttributeMaxDynamicSharedMemorySize,
                         FLASH_SMEM_BYTES);

    // QKV projections
    sgemm_nt<<<dim3((NHQ*HD)/128,  MROWS/128), 256>>>(hidden, wq, q, MROWS, NHQ*HD,  HID);
    sgemm_nt<<<dim3((NHKV*HD)/128, MROWS/128), 256>>>(hidden, wk, k, MROWS, NHKV*HD, HID);
    sgemm_nt<<<dim3((NHKV*HD)/128, MROWS/128), 256>>>(hidden, wv, v, MROWS, NHKV*HD, HID);
    // QK RMSNorm + RoPE
    norm_rope<<<(MROWS*NHQ *32 + 255) / 256, 256>>>(q, qw, NHQ);
    norm_rope<<<(MROWS*NHKV*32 + 255) / 256, 256>>>(k, kw, NHKV);
    // sliding-window flash attention
    flash_fwd<<<dim3(SEQ/BQ, NHQ, NB), 256, FLASH_SMEM_BYTES>>>(q, k, v, attn);
    // output projection
    sgemm_nt<<<dim3(HID/128, MROWS/128), 256>>>(attn, wo, out, MROWS, HID, NHQ*HD);
}

// round 2
// speedup vs baseline: 2.2975x; 2.2975x over previous
#include <cuda_runtime.h>
#include <math.h>

#define NB 2
#define SEQ 2048
#define HID 2048
#define NHQ 16
#define NHKV 8
#define HD 128
#define WIN 1024
#define MROWS (NB*SEQ)   // 4096

// ---------------- scratch (static device globals; no cudaMalloc allowed) ----
__device__ float g_q[(size_t)MROWS * NHQ * HD];     // 33.5 MB
__device__ float g_k[(size_t)MROWS * NHKV * HD];    // 16.8 MB
__device__ float g_v[(size_t)MROWS * NHKV * HD];    // 16.8 MB
__device__ float g_attn[(size_t)MROWS * NHQ * HD];  // 33.5 MB
__device__ float g_rope_cos[SEQ * 64];
__device__ float g_rope_sin[SEQ * 64];

// ---------------------------------------------------------------------------
// RoPE table: cos/sin(pos * theta^(-d/64)) computed once in fp64.
// ---------------------------------------------------------------------------
__global__ void rope_table(float* __restrict__ ct, float* __restrict__ st)
{
    int idx = blockIdx.x * 256 + threadIdx.x;
    if (idx >= SEQ * 64) return;
    int pos = idx >> 6;
    int d   = idx & 63;
    double ang = (double)pos * pow(10000.0, -(double)d / 64.0);
    double s, c;
    sincos(ang, &s, &c);
    ct[idx] = (float)c;
    st[idx] = (float)s;
}

// ---------------------------------------------------------------------------
// tf32 tensor-core GEMM (NT): C[M,N] = A[M,K] @ W[N,K]^T.
// BM=BN=128, BK=16, 256 threads (8 warps, 4x2 warp grid, 32x64 warp tile).
// mma.sync.aligned.m16n8k8.row.col.f32.tf32.tf32.f32
// ---------------------------------------------------------------------------
__device__ __forceinline__ unsigned f2tf32(float x) {
    unsigned r;
    asm("cvt.rna.tf32.f32 %0, %1;" : "=r"(r) : "f"(x));
    return r;
}

__device__ __forceinline__ void mma_tf32(float c[4], const unsigned a[4],
                                         const unsigned b[2]) {
    asm volatile(
        "mma.sync.aligned.m16n8k8.row.col.f32.tf32.tf32.f32 "
        "{%0,%1,%2,%3}, {%4,%5,%6,%7}, {%8,%9}, {%0,%1,%2,%3};\n"
        : "+f"(c[0]), "+f"(c[1]), "+f"(c[2]), "+f"(c[3])
        : "r"(a[0]), "r"(a[1]), "r"(a[2]), "r"(a[3]), "r"(b[0]), "r"(b[1]));
}

#define SSTR 136   // 128 + 8 pad: k-row stride of 8 banks -> conflict-free frag loads

__global__ __launch_bounds__(256) void gemm_tf32(
    const float* __restrict__ A, const float* __restrict__ Wt,
    float* __restrict__ C, int M, int N, int K)
{
    __shared__ unsigned As[16][SSTR];
    __shared__ unsigned Bs[16][SSTR];
    const int tid  = threadIdx.x;
    const int lane = tid & 31;
    const int warp = tid >> 5;
    const int wm = warp >> 1;       // 0..3 (M)
    const int wn = warp & 1;        // 0..1 (N)
    const int gid = lane >> 2;      // 0..7
    const int tig = lane & 3;       // 0..3
    const int m0 = blockIdx.y << 7;
    const int n0 = blockIdx.x << 7;
    const int lr = tid >> 1;        // 0..127
    const int lc = (tid & 1) << 3;  // 0 or 8
    const float* Ag = A  + (size_t)(m0 + lr) * K + lc;
    const float* Wg = Wt + (size_t)(n0 + lr) * K + lc;

    float acc[2][8][4] = {};

    for (int k0 = 0; k0 < K; k0 += 16) {
        float4 a0 = *(const float4*)(Ag + k0);
        float4 a1 = *(const float4*)(Ag + k0 + 4);
        float4 b0 = *(const float4*)(Wg + k0);
        float4 b1 = *(const float4*)(Wg + k0 + 4);
        __syncthreads();
        As[lc+0][lr]=f2tf32(a0.x); As[lc+1][lr]=f2tf32(a0.y);
        As[lc+2][lr]=f2tf32(a0.z); As[lc+3][lr]=f2tf32(a0.w);
        As[lc+4][lr]=f2tf32(a1.x); As[lc+5][lr]=f2tf32(a1.y);
        As[lc+6][lr]=f2tf32(a1.z); As[lc+7][lr]=f2tf32(a1.w);
        Bs[lc+0][lr]=f2tf32(b0.x); Bs[lc+1][lr]=f2tf32(b0.y);
        Bs[lc+2][lr]=f2tf32(b0.z); Bs[lc+3][lr]=f2tf32(b0.w);
        Bs[lc+4][lr]=f2tf32(b1.x); Bs[lc+5][lr]=f2tf32(b1.y);
        Bs[lc+6][lr]=f2tf32(b1.z); Bs[lc+7][lr]=f2tf32(b1.w);
        __syncthreads();
        #pragma unroll
        for (int ks = 0; ks < 2; ks++) {
            const int kb = ks << 3;
            unsigned afr[2][4], bfr[8][2];
            #pragma unroll
            for (int mi = 0; mi < 2; mi++) {
                int mr = (wm << 5) + (mi << 4);
                afr[mi][0] = As[kb + tig    ][mr + gid];
                afr[mi][1] = As[kb + tig    ][mr + gid + 8];
                afr[mi][2] = As[kb + tig + 4][mr + gid];
                afr[mi][3] = As[kb + tig + 4][mr + gid + 8];
            }
            #pragma unroll
            for (int ni = 0; ni < 8; ni++) {
                int nc = (wn << 6) + (ni << 3);
                bfr[ni][0] = Bs[kb + tig    ][nc + gid];
                bfr[ni][1] = Bs[kb + tig + 4][nc + gid];
            }
            #pragma unroll
            for (int mi = 0; mi < 2; mi++)
                #pragma unroll
                for (int ni = 0; ni < 8; ni++)
                    mma_tf32(acc[mi][ni], afr[mi], bfr[ni]);
        }
    }
    // write C: rows m0+wm*32+mi*16+gid(+8), cols n0+wn*64+ni*8+2*tig(+1)
    #pragma unroll
    for (int mi = 0; mi < 2; mi++) {
        int r0 = m0 + (wm << 5) + (mi << 4) + gid;
        #pragma unroll
        for (int ni = 0; ni < 8; ni++) {
            int cc = n0 + (wn << 6) + (ni << 3) + (tig << 1);
            *(float2*)(C + (size_t)r0 * N + cc) =
                make_float2(acc[mi][ni][0], acc[mi][ni][1]);
            *(float2*)(C + (size_t)(r0 + 8) * N + cc) =
                make_float2(acc[mi][ni][2], acc[mi][ni][3]);
        }
    }
}

// ---------------------------------------------------------------------------
// Gemma RMSNorm (x * rsqrt(mean(x^2)+eps) * (1+w)) + RoPE via table.
// One warp per (row, head). Lane owns dims {l, l+32, l+64, l+96}.
// ---------------------------------------------------------------------------
__global__ __launch_bounds__(256) void norm_rope(
    float* __restrict__ x, const float* __restrict__ w, int n_heads,
    const float* __restrict__ ct, const float* __restrict__ st)
{
    int gw   = (blockIdx.x * 256 + threadIdx.x) >> 5;
    int lane = threadIdx.x & 31;
    if (gw >= MROWS * n_heads) return;
    int m = gw / n_heads;
    int h = gw - m * n_heads;
    int pos = m & (SEQ - 1);
    float* row = x + (size_t)m * (n_heads * HD) + h * HD;
    float x0 = row[lane], x1 = row[lane+32], x2 = row[lane+64], x3 = row[lane+96];
    float ss = x0*x0 + x1*x1 + x2*x2 + x3*x3;
    #pragma unroll
    for (int o = 16; o; o >>= 1) ss += __shfl_xor_sync(0xffffffffu, ss, o);
    float rstd = rsqrtf(ss * (1.0f / HD) + 1e-6f);
    float y0 = x0 * rstd * (1.f + w[lane]);
    float y1 = x1 * rstd * (1.f + w[lane+32]);
    float y2 = x2 * rstd * (1.f + w[lane+64]);
    float y3 = x3 * rstd * (1.f + w[lane+96]);
    float c0 = ct[pos*64 + lane],      s0 = st[pos*64 + lane];
    float c1 = ct[pos*64 + lane + 32], s1 = st[pos*64 + lane + 32];
    row[lane]      = y0 * c0 - y2 * s0;   // d<64:  x*cos - x[d+64]*sin
    row[lane+64]   = y2 * c0 + y0 * s0;   // d>=64: x*cos + x[d-64]*sin
    row[lane+32]   = y1 * c1 - y3 * s1;
    row[lane+96]   = y3 * c1 + y1 * s1;
}

// ---------------------------------------------------------------------------
// Flash attention, sliding-window causal, GQA (q head h -> kv head h/2).
// BQ=64 queries x BKT=64 keys per iteration, 256 threads. fp32 SIMT.
// ---------------------------------------------------------------------------
#define BQ 64
#define BKT 64
#define FLASH_SMEM_FLOATS (64*129 + 128*65 + 64*128 + 64*65 + 3*64)
#define FLASH_SMEM_BYTES  (FLASH_SMEM_FLOATS * 4)

__global__ __launch_bounds__(256) void flash_fwd(
    const float* __restrict__ q, const float* __restrict__ k,
    const float* __restrict__ v, float* __restrict__ o)
{
    extern __shared__ float smem[];
    float* Qs  = smem;                 // [64][129]
    float* KsT = Qs  + 64 * 129;       // [128][65]
    float* Vs  = KsT + 128 * 65;       // [64][128]
    float* Ss  = Vs  + 64 * 128;       // [64][65]
    float* m_s = Ss  + 64 * 65;
    float* l_s = m_s + 64;
    float* c_s = l_s + 64;

    const int tid = threadIdx.x;
    const int q0  = blockIdx.x * BQ;
    const int h   = blockIdx.y;
    const int b   = blockIdx.z;
    const int hk  = h >> 1;                     // repeat_interleave(groups=2)
    const float* qbase = q + (size_t)b * SEQ * (NHQ  * HD) + h  * HD;
    const float* kbase = k + (size_t)b * SEQ * (NHKV * HD) + hk * HD;
    const float* vbase = v + (size_t)b * SEQ * (NHKV * HD) + hk * HD;

    #pragma unroll
    for (int rep = 0; rep < 8; rep++) {
        int idx = rep * 256 + tid;
        int r   = idx >> 5;
        int dc  = (idx & 31) << 2;
        float4 va = *(const float4*)(qbase + (size_t)(q0 + r) * (NHQ * HD) + dc);
        float* dst = Qs + r * 129 + dc;
        dst[0] = va.x; dst[1] = va.y; dst[2] = va.z; dst[3] = va.w;
    }
    if (tid < 64) { m_s[tid] = -1e30f; l_s[tid] = 0.f; }

    float acc[8][4] = {};
    const int pv_r0 = (tid >> 5) << 3;
    const int pv_d0 = (tid & 31) << 2;
    const int qk_r0 = (tid >> 4) << 2;
    const int qk_c0 = (tid & 15) << 2;
    const int sm_r  = tid >> 2;
    const int sm_g  = tid & 3;

    int jlo = q0 - (WIN - 1); if (jlo < 0) jlo = 0;
    const int jstart = jlo & ~(BKT - 1);
    const float scale = 0.08838834764831845f;   // 1/sqrt(128)

    for (int j0 = jstart; j0 <= q0 + BQ - 1; j0 += BKT) {
        __syncthreads();
        #pragma unroll
        for (int sub = 0; sub < 8; sub++) {
            int r = tid >> 2;
            int c = (tid & 3) << 2;
            float4 kv = *(const float4*)(kbase + (size_t)(j0 + r) * (NHKV * HD) + sub * 16 + c);
            int dbase = sub * 16 + c;
            KsT[(dbase+0)*65 + r] = kv.x;
            KsT[(dbase+1)*65 + r] = kv.y;
            KsT[(dbase+2)*65 + r] = kv.z;
            KsT[(dbase+3)*65 + r] = kv.w;
        }
        #pragma unroll
        for (int rep = 0; rep < 8; rep++) {
            int idx = rep * 256 + tid;
            int r   = idx >> 5;
            int dc  = (idx & 31) << 2;
            *(float4*)(Vs + r * 128 + dc) =
                *(const float4*)(vbase + (size_t)(j0 + r) * (NHKV * HD) + dc);
        }
        __syncthreads();
        {
            float aq[4][4] = {};
            #pragma unroll 8
            for (int kk = 0; kk < 128; kk++) {
                float ra[4], rb[4];
                #pragma unroll
                for (int i = 0; i < 4; i++) ra[i] = Qs[(qk_r0 + i) * 129 + kk];
                #pragma unroll
                for (int j = 0; j < 4; j++) rb[j] = KsT[kk * 65 + qk_c0 + j];
                #pragma unroll
                for (int i = 0; i < 4; i++)
                    #pragma unroll
                    for (int j = 0; j < 4; j++)
                        aq[i][j] = fmaf(ra[i], rb[j], aq[i][j]);
            }
            #pragma unroll
            for (int i = 0; i < 4; i++) {
                int qi = q0 + qk_r0 + i;
                #pragma unroll
                for (int j = 0; j < 4; j++) {
                    int kj = j0 + qk_c0 + j;
                    bool valid = (kj <= qi) && (kj > qi - WIN);
                    Ss[(qk_r0 + i) * 65 + qk_c0 + j] = valid ? aq[i][j] * scale : -1e30f;
                }
            }
        }
        __syncthreads();
        {
            float mx = -1e30f;
            #pragma unroll
            for (int u = 0; u < 16; u++) mx = fmaxf(mx, Ss[sm_r * 65 + sm_g * 16 + u]);
            mx = fmaxf(mx, __shfl_xor_sync(0xffffffffu, mx, 1));
            mx = fmaxf(mx, __shfl_xor_sync(0xffffffffu, mx, 2));
            float m_old = m_s[sm_r];
            float m_new = fmaxf(m_old, mx);
            float corr  = __expf(m_old - m_new);
            float psum  = 0.f;
            #pragma unroll
            for (int u = 0; u < 16; u++) {
                float s = Ss[sm_r * 65 + sm_g * 16 + u];
                float p = (s > -1e29f) ? __expf(s - m_new) : 0.f;
                Ss[sm_r * 65 + sm_g * 16 + u] = p;
                psum += p;
            }
            psum += __shfl_xor_sync(0xffffffffu, psum, 1);
            psum += __shfl_xor_sync(0xffffffffu, psum, 2);
            if (sm_g == 0) {
                m_s[sm_r] = m_new;
                c_s[sm_r] = corr;
                l_s[sm_r] = l_s[sm_r] * corr + psum;
            }
        }
        __syncthreads();
        {
            #pragma unroll
            for (int i = 0; i < 8; i++) {
                float corr = c_s[pv_r0 + i];
                #pragma unroll
                for (int u = 0; u < 4; u++) acc[i][u] *= corr;
            }
            #pragma unroll 4
            for (int j = 0; j < BKT; j++) {
                float4 vv = *(const float4*)(Vs + j * 128 + pv_d0);
                #pragma unroll
                for (int i = 0; i < 8; i++) {
                    float p = Ss[(pv_r0 + i) * 65 + j];
                    acc[i][0] = fmaf(p, vv.x, acc[i][0]);
                    acc[i][1] = fmaf(p, vv.y, acc[i][1]);
                    acc[i][2] = fmaf(p, vv.z, acc[i][2]);
                    acc[i][3] = fmaf(p, vv.w, acc[i][3]);
                }
            }
        }
    }
    float* obase = o + (size_t)b * SEQ * (NHQ * HD) + h * HD;
    #pragma unroll
    for (int i = 0; i < 8; i++) {
        float inv = 1.0f / l_s[pv_r0 + i];
        *(float4*)(obase + (size_t)(q0 + pv_r0 + i) * (NHQ * HD) + pv_d0) =
            make_float4(acc[i][0]*inv, acc[i][1]*inv, acc[i][2]*inv, acc[i][3]*inv);
    }
}

// ---------------------------------------------------------------------------
extern "C" void kernel_launch(void* const* d_in, const int* in_sizes, int n_in,
                              void* d_out, int out_size)
{
    const float* hidden = (const float*)d_in[0];
    const float* wq = (const float*)d_in[1];
    const float* wk = (const float*)d_in[2];
    const float* wv = (const float*)d_in[3];
    const float* wo = (const float*)d_in[4];
    const float* qw = (const float*)d_in[5];
    const float* kw = (const float*)d_in[6];
    float* out = (float*)d_out;

    float *q, *k, *v, *attn, *ct, *st;
    cudaGetSymbolAddress((void**)&q,    g_q);
    cudaGetSymbolAddress((void**)&k,    g_k);
    cudaGetSymbolAddress((void**)&v,    g_v);
    cudaGetSymbolAddress((void**)&attn, g_attn);
    cudaGetSymbolAddress((void**)&ct,   g_rope_cos);
    cudaGetSymbolAddress((void**)&st,   g_rope_sin);

    cudaFuncSetAttribute(flash_fwd, cudaFuncAttributeMaxDynamicSharedMemorySize,
                         FLASH_SMEM_BYTES);

    // RoPE tables (fp64 once, tiny)
    rope_table<<<(SEQ*64 + 255) / 256, 256>>>(ct, st);
    // QKV projections (tf32 tensor cores)
    gemm_tf32<<<dim3((NHQ*HD)/128,  MROWS/128), 256>>>(hidden, wq, q, MROWS, NHQ*HD,  HID);
    gemm_tf32<<<dim3((NHKV*HD)/128, MROWS/128), 256>>>(hidden, wk, k, MROWS, NHKV*HD, HID);
    gemm_tf32<<<dim3((NHKV*HD)/128, MROWS/128), 256>>>(hidden, wv, v, MROWS, NHKV*HD, HID);
    // QK RMSNorm + RoPE
    norm_rope<<<(MROWS*NHQ *32 + 255) / 256, 256>>>(q, qw, NHQ,  ct, st);
    norm_rope<<<(MROWS*NHKV*32 + 255) / 256, 256>>>(k, kw, NHKV, ct, st);
    // sliding-window flash attention
    flash_fwd<<<dim3(SEQ/BQ, NHQ, NB), 256, FLASH_SMEM_BYTES>>>(q, k, v, attn);
    // output projection
    gemm_tf32<<<dim3(HID/128, MROWS/128), 256>>>(attn, wo, out, MROWS, HID, NHQ*HD);
}

// round 3
// speedup vs baseline: 3.0659x; 1.3345x over previous
#include <cuda_runtime.h>
#include <math.h>

#define NB 2
#define SEQ 2048
#define HID 2048
#define NHQ 16
#define NHKV 8
#define HD 128
#define WIN 1024
#define MROWS (NB*SEQ)   // 4096

// ---------------- scratch (static device globals; no cudaMalloc allowed) ----
__device__ float g_q[(size_t)MROWS * NHQ * HD];     // 33.5 MB
__device__ float g_k[(size_t)MROWS * NHKV * HD];    // 16.8 MB
__device__ float g_v[(size_t)MROWS * NHKV * HD];    // 16.8 MB
__device__ float g_attn[(size_t)MROWS * NHQ * HD];  // 33.5 MB
__device__ float g_rope_cos[SEQ * 64];
__device__ float g_rope_sin[SEQ * 64];

// ---------------------------------------------------------------------------
__global__ void rope_table(float* __restrict__ ct, float* __restrict__ st)
{
    int idx = blockIdx.x * 256 + threadIdx.x;
    if (idx >= SEQ * 64) return;
    int pos = idx >> 6;
    int d   = idx & 63;
    double ang = (double)pos * pow(10000.0, -(double)d / 64.0);
    double s, c;
    sincos(ang, &s, &c);
    ct[idx] = (float)c;
    st[idx] = (float)s;
}

// ---------------------------------------------------------------------------
// tf32 helpers (fragment layout validated in gemm_tf32, R2)
// ---------------------------------------------------------------------------
__device__ __forceinline__ unsigned f2tf32(float x) {
    unsigned r;
    asm("cvt.rna.tf32.f32 %0, %1;" : "=r"(r) : "f"(x));
    return r;
}

__device__ __forceinline__ void mma_tf32(float c[4], const unsigned a[4],
                                         const unsigned b[2]) {
    asm volatile(
        "mma.sync.aligned.m16n8k8.row.col.f32.tf32.tf32.f32 "
        "{%0,%1,%2,%3}, {%4,%5,%6,%7}, {%8,%9}, {%0,%1,%2,%3};\n"
        : "+f"(c[0]), "+f"(c[1]), "+f"(c[2]), "+f"(c[3])
        : "r"(a[0]), "r"(a[1]), "r"(a[2]), "r"(a[3]), "r"(b[0]), "r"(b[1]));
}

// ---------------------------------------------------------------------------
// tf32 tensor-core GEMM (NT): C[M,N] = A[M,K] @ W[N,K]^T. (unchanged from R2)
// ---------------------------------------------------------------------------
#define SSTR 136

__global__ __launch_bounds__(256) void gemm_tf32(
    const float* __restrict__ A, const float* __restrict__ Wt,
    float* __restrict__ C, int M, int N, int K)
{
    __shared__ unsigned As[16][SSTR];
    __shared__ unsigned Bs[16][SSTR];
    const int tid  = threadIdx.x;
    const int lane = tid & 31;
    const int warp = tid >> 5;
    const int wm = warp >> 1;
    const int wn = warp & 1;
    const int gid = lane >> 2;
    const int tig = lane & 3;
    const int m0 = blockIdx.y << 7;
    const int n0 = blockIdx.x << 7;
    const int lr = tid >> 1;
    const int lc = (tid & 1) << 3;
    const float* Ag = A  + (size_t)(m0 + lr) * K + lc;
    const float* Wg = Wt + (size_t)(n0 + lr) * K + lc;

    float acc[2][8][4] = {};

    for (int k0 = 0; k0 < K; k0 += 16) {
        float4 a0 = *(const float4*)(Ag + k0);
        float4 a1 = *(const float4*)(Ag + k0 + 4);
        float4 b0 = *(const float4*)(Wg + k0);
        float4 b1 = *(const float4*)(Wg + k0 + 4);
        __syncthreads();
        As[lc+0][lr]=f2tf32(a0.x); As[lc+1][lr]=f2tf32(a0.y);
        As[lc+2][lr]=f2tf32(a0.z); As[lc+3][lr]=f2tf32(a0.w);
        As[lc+4][lr]=f2tf32(a1.x); As[lc+5][lr]=f2tf32(a1.y);
        As[lc+6][lr]=f2tf32(a1.z); As[lc+7][lr]=f2tf32(a1.w);
        Bs[lc+0][lr]=f2tf32(b0.x); Bs[lc+1][lr]=f2tf32(b0.y);
        Bs[lc+2][lr]=f2tf32(b0.z); Bs[lc+3][lr]=f2tf32(b0.w);
        Bs[lc+4][lr]=f2tf32(b1.x); Bs[lc+5][lr]=f2tf32(b1.y);
        Bs[lc+6][lr]=f2tf32(b1.z); Bs[lc+7][lr]=f2tf32(b1.w);
        __syncthreads();
        #pragma unroll
        for (int ks = 0; ks < 2; ks++) {
            const int kb = ks << 3;
            unsigned afr[2][4], bfr[8][2];
            #pragma unroll
            for (int mi = 0; mi < 2; mi++) {
                int mr = (wm << 5) + (mi << 4);
                afr[mi][0] = As[kb + tig    ][mr + gid];
                afr[mi][1] = As[kb + tig    ][mr + gid + 8];
                afr[mi][2] = As[kb + tig + 4][mr + gid];
                afr[mi][3] = As[kb + tig + 4][mr + gid + 8];
            }
            #pragma unroll
            for (int ni = 0; ni < 8; ni++) {
                int nc = (wn << 6) + (ni << 3);
                bfr[ni][0] = Bs[kb + tig    ][nc + gid];
                bfr[ni][1] = Bs[kb + tig + 4][nc + gid];
            }
            #pragma unroll
            for (int mi = 0; mi < 2; mi++)
                #pragma unroll
                for (int ni = 0; ni < 8; ni++)
                    mma_tf32(acc[mi][ni], afr[mi], bfr[ni]);
        }
    }
    #pragma unroll
    for (int mi = 0; mi < 2; mi++) {
        int r0 = m0 + (wm << 5) + (mi << 4) + gid;
        #pragma unroll
        for (int ni = 0; ni < 8; ni++) {
            int cc = n0 + (wn << 6) + (ni << 3) + (tig << 1);
            *(float2*)(C + (size_t)r0 * N + cc) =
                make_float2(acc[mi][ni][0], acc[mi][ni][1]);
            *(float2*)(C + (size_t)(r0 + 8) * N + cc) =
                make_float2(acc[mi][ni][2], acc[mi][ni][3]);
        }
    }
}

// ---------------------------------------------------------------------------
// RMSNorm + RoPE via table (unchanged from R2)
// ---------------------------------------------------------------------------
__global__ __launch_bounds__(256) void norm_rope(
    float* __restrict__ x, const float* __restrict__ w, int n_heads,
    const float* __restrict__ ct, const float* __restrict__ st)
{
    int gw   = (blockIdx.x * 256 + threadIdx.x) >> 5;
    int lane = threadIdx.x & 31;
    if (gw >= MROWS * n_heads) return;
    int m = gw / n_heads;
    int h = gw - m * n_heads;
    int pos = m & (SEQ - 1);
    float* row = x + (size_t)m * (n_heads * HD) + h * HD;
    float x0 = row[lane], x1 = row[lane+32], x2 = row[lane+64], x3 = row[lane+96];
    float ss = x0*x0 + x1*x1 + x2*x2 + x3*x3;
    #pragma unroll
    for (int o = 16; o; o >>= 1) ss += __shfl_xor_sync(0xffffffffu, ss, o);
    float rstd = rsqrtf(ss * (1.0f / HD) + 1e-6f);
    float y0 = x0 * rstd * (1.f + w[lane]);
    float y1 = x1 * rstd * (1.f + w[lane+32]);
    float y2 = x2 * rstd * (1.f + w[lane+64]);
    float y3 = x3 * rstd * (1.f + w[lane+96]);
    float c0 = ct[pos*64 + lane],      s0 = st[pos*64 + lane];
    float c1 = ct[pos*64 + lane + 32], s1 = st[pos*64 + lane + 32];
    row[lane]      = y0 * c0 - y2 * s0;
    row[lane+64]   = y2 * c0 + y0 * s0;
    row[lane+32]   = y1 * c1 - y3 * s1;
    row[lane+96]   = y3 * c1 + y1 * s1;
}

// ---------------------------------------------------------------------------
// Flash attention with tf32 mma. Sliding-window causal, GQA h->h/2.
// BQ=BKT=64, 256 threads, warp grid 4(m) x 2(n).
// smem strides chosen so fragment LDS hits 32 distinct banks:
//   Qs (row g, col t)  stride 132 (=4 mod 32 -> banks 4g+t)
//   KsT/Vs (row t, col g) stride 72/136 (=8 mod 32 -> banks 8t+g)
//   Ss (row g, col t)  stride 68  (=4 mod 32)
// ---------------------------------------------------------------------------
#define FBQ 64
#define FBK 64
#define QSTR 132
#define KSTR 72
#define VSTR 136
#define PSTR 68
#define FLASH_WORDS (64*QSTR + 128*KSTR + 64*VSTR + 64*PSTR + 3*64)
#define FLASH_BYTES (FLASH_WORDS * 4)

__global__ __launch_bounds__(256) void flash_tf32(
    const float* __restrict__ q, const float* __restrict__ k,
    const float* __restrict__ v, float* __restrict__ o)
{
    extern __shared__ unsigned smu[];
    unsigned* Qs  = smu;                    // [64][QSTR] tf32 bits (pre-scaled)
    unsigned* KsT = Qs  + 64 * QSTR;        // [128][KSTR] d-major tf32
    unsigned* Vs  = KsT + 128 * KSTR;       // [64][VSTR] tf32
    float*    Ss  = (float*)(Vs + 64 * VSTR); // [64][PSTR] scores -> P tf32 bits
    float* m_s = Ss + 64 * PSTR;
    float* l_s = m_s + 64;
    float* c_s = l_s + 64;
    unsigned* Psu = (unsigned*)Ss;

    const int tid  = threadIdx.x;
    const int lane = tid & 31;
    const int warp = tid >> 5;
    const int wm = warp >> 1;        // 0..3
    const int wn = warp & 1;         // 0..1
    const int g  = lane >> 2;        // 0..7
    const int t  = lane & 3;         // 0..3
    const int mrow = wm << 4;        // warp's 16-row block

    const int q0 = blockIdx.x * FBQ;
    const int h  = blockIdx.y;
    const int b  = blockIdx.z;
    const int hk = h >> 1;
    const float* qbase = q + (size_t)b * SEQ * (NHQ  * HD) + h  * HD;
    const float* kbase = k + (size_t)b * SEQ * (NHKV * HD) + hk * HD;
    const float* vbase = v + (size_t)b * SEQ * (NHKV * HD) + hk * HD;
    const float scale = 0.08838834764831845f;   // 1/sqrt(128), folded into Q

    // ---- load Q (scaled) -> Qs ----
    #pragma unroll
    for (int rep = 0; rep < 8; rep++) {
        int idx = rep * 256 + tid;
        int r   = idx >> 5;
        int dc  = (idx & 31) << 2;
        float4 va = *(const float4*)(qbase + (size_t)(q0 + r) * (NHQ * HD) + dc);
        unsigned* dst = Qs + r * QSTR + dc;
        dst[0] = f2tf32(va.x * scale); dst[1] = f2tf32(va.y * scale);
        dst[2] = f2tf32(va.z * scale); dst[3] = f2tf32(va.w * scale);
    }
    if (tid < 64) { m_s[tid] = -1e30f; l_s[tid] = 0.f; }
    __syncthreads();

    // ---- persistent Q fragments: 16 k-chunks x 4 regs ----
    unsigned qf[16][4];
    #pragma unroll
    for (int kc = 0; kc < 16; kc++) {
        int kb = kc << 3;
        qf[kc][0] = Qs[(mrow + g    ) * QSTR + kb + t];
        qf[kc][1] = Qs[(mrow + g + 8) * QSTR + kb + t];
        qf[kc][2] = Qs[(mrow + g    ) * QSTR + kb + t + 4];
        qf[kc][3] = Qs[(mrow + g + 8) * QSTR + kb + t + 4];
    }

    float oacc[8][4] = {};
    const int sm_r = tid >> 2;
    const int sm_g = tid & 3;

    int jlo = q0 - (WIN - 1); if (jlo < 0) jlo = 0;
    const int jstart = jlo & ~(FBK - 1);

    for (int j0 = jstart; j0 <= q0; j0 += FBK) {
        __syncthreads();
        // ---- K transpose load (d-major) + V load, tf32 ----
        {
            int r  = tid >> 2;
            int c4 = (tid & 3) << 2;
            #pragma unroll
            for (int sub = 0; sub < 8; sub++) {
                float4 kv = *(const float4*)(kbase + (size_t)(j0 + r) * (NHKV * HD) + sub * 16 + c4);
                int dbase = sub * 16 + c4;
                KsT[(dbase+0)*KSTR + r] = f2tf32(kv.x);
                KsT[(dbase+1)*KSTR + r] = f2tf32(kv.y);
                KsT[(dbase+2)*KSTR + r] = f2tf32(kv.z);
                KsT[(dbase+3)*KSTR + r] = f2tf32(kv.w);
            }
        }
        #pragma unroll
        for (int rep = 0; rep < 8; rep++) {
            int idx = rep * 256 + tid;
            int r   = idx >> 5;
            int dc  = (idx & 31) << 2;
            float4 vv = *(const float4*)(vbase + (size_t)(j0 + r) * (NHKV * HD) + dc);
            unsigned* dst = Vs + r * VSTR + dc;
            dst[0] = f2tf32(vv.x); dst[1] = f2tf32(vv.y);
            dst[2] = f2tf32(vv.z); dst[3] = f2tf32(vv.w);
        }
        __syncthreads();

        // ---- S = Q K^T (warp tile 16x32) ----
        float sacc[4][4] = {};
        #pragma unroll
        for (int kc = 0; kc < 16; kc++) {
            int kb = kc << 3;
            unsigned bf[4][2];
            #pragma unroll
            for (int ni = 0; ni < 4; ni++) {
                int jn = (wn << 5) + (ni << 3);
                bf[ni][0] = KsT[(kb + t    ) * KSTR + jn + g];
                bf[ni][1] = KsT[(kb + t + 4) * KSTR + jn + g];
            }
            #pragma unroll
            for (int ni = 0; ni < 4; ni++)
                mma_tf32(sacc[ni], qf[kc], bf[ni]);
        }
        #pragma unroll
        for (int ni = 0; ni < 4; ni++) {
            int jn = (wn << 5) + (ni << 3) + (t << 1);
            Ss[(mrow + g    ) * PSTR + jn]     = sacc[ni][0];
            Ss[(mrow + g    ) * PSTR + jn + 1] = sacc[ni][1];
            Ss[(mrow + g + 8) * PSTR + jn]     = sacc[ni][2];
            Ss[(mrow + g + 8) * PSTR + jn + 1] = sacc[ni][3];
        }
        __syncthreads();

        // ---- online softmax (4 threads/row), mask here ----
        {
            int qi = q0 + sm_r;
            float sv[16];
            float mx = -1e30f;
            #pragma unroll
            for (int u = 0; u < 16; u++) {
                int kj = j0 + sm_g * 16 + u;
                float s = Ss[sm_r * PSTR + sm_g * 16 + u];
                bool valid = (kj <= qi) && (kj > qi - WIN);
                sv[u] = valid ? s : -1e30f;
                mx = fmaxf(mx, sv[u]);
            }
            mx = fmaxf(mx, __shfl_xor_sync(0xffffffffu, mx, 1));
            mx = fmaxf(mx, __shfl_xor_sync(0xffffffffu, mx, 2));
            float m_old = m_s[sm_r];
            float m_new = fmaxf(m_old, mx);
            float corr  = __expf(m_old - m_new);
            float psum  = 0.f;
            #pragma unroll
            for (int u = 0; u < 16; u++) {
                float p = (sv[u] > -1e29f) ? __expf(sv[u] - m_new) : 0.f;
                Psu[sm_r * PSTR + sm_g * 16 + u] = f2tf32(p);
                psum += p;
            }
            psum += __shfl_xor_sync(0xffffffffu, psum, 1);
            psum += __shfl_xor_sync(0xffffffffu, psum, 2);
            if (sm_g == 0) {
                m_s[sm_r] = m_new;
                c_s[sm_r] = corr;
                l_s[sm_r] = l_s[sm_r] * corr + psum;
            }
        }
        __syncthreads();

        // ---- O = O*corr + P V (warp tile 16x64) ----
        {
            float cl = c_s[mrow + g];
            float ch = c_s[mrow + g + 8];
            #pragma unroll
            for (int ni = 0; ni < 8; ni++) {
                oacc[ni][0] *= cl; oacc[ni][1] *= cl;
                oacc[ni][2] *= ch; oacc[ni][3] *= ch;
            }
            #pragma unroll
            for (int kc = 0; kc < 8; kc++) {
                int kb = kc << 3;
                unsigned af[4];
                af[0] = Psu[(mrow + g    ) * PSTR + kb + t];
                af[1] = Psu[(mrow + g + 8) * PSTR + kb + t];
                af[2] = Psu[(mrow + g    ) * PSTR + kb + t + 4];
                af[3] = Psu[(mrow + g + 8) * PSTR + kb + t + 4];
                #pragma unroll
                for (int ni = 0; ni < 8; ni++) {
                    int dn = (wn << 6) + (ni << 3);
                    unsigned bb[2];
                    bb[0] = Vs[(kb + t    ) * VSTR + dn + g];
                    bb[1] = Vs[(kb + t + 4) * VSTR + dn + g];
                    mma_tf32(oacc[ni], af, bb);
                }
            }
        }
    }

    // ---- epilogue: divide by l, store ----
    float il = 1.0f / l_s[mrow + g];
    float ih = 1.0f / l_s[mrow + g + 8];
    float* obase = o + (size_t)b * SEQ * (NHQ * HD) + h * HD;
    int rlo = q0 + mrow + g;
    int rhi = rlo + 8;
    #pragma unroll
    for (int ni = 0; ni < 8; ni++) {
        int dn = (wn << 6) + (ni << 3) + (t << 1);
        *(float2*)(obase + (size_t)rlo * (NHQ * HD) + dn) =
            make_float2(oacc[ni][0] * il, oacc[ni][1] * il);
        *(float2*)(obase + (size_t)rhi * (NHQ * HD) + dn) =
            make_float2(oacc[ni][2] * ih, oacc[ni][3] * ih);
    }
}

// ---------------------------------------------------------------------------
extern "C" void kernel_launch(void* const* d_in, const int* in_sizes, int n_in,
                              void* d_out, int out_size)
{
    const float* hidden = (const float*)d_in[0];
    const float* wq = (const float*)d_in[1];
    const float* wk = (const float*)d_in[2];
    const float* wv = (const float*)d_in[3];
    const float* wo = (const float*)d_in[4];
    const float* qw = (const float*)d_in[5];
    const float* kw = (const float*)d_in[6];
    float* out = (float*)d_out;

    float *q, *k, *v, *attn, *ct, *st;
    cudaGetSymbolAddress((void**)&q,    g_q);
    cudaGetSymbolAddress((void**)&k,    g_k);
    cudaGetSymbolAddress((void**)&v,    g_v);
    cudaGetSymbolAddress((void**)&attn, g_attn);
    cudaGetSymbolAddress((void**)&ct,   g_rope_cos);
    cudaGetSymbolAddress((void**)&st,   g_rope_sin);

    cudaFuncSetAttribute(flash_tf32, cudaFuncAttributeMaxDynamicSharedMemorySize,
                         FLASH_BYTES);

    rope_table<<<(SEQ*64 + 255) / 256, 256>>>(ct, st);
    gemm_tf32<<<dim3((NHQ*HD)/128,  MROWS/128), 256>>>(hidden, wq, q, MROWS, NHQ*HD,  HID);
    gemm_tf32<<<dim3((NHKV*HD)/128, MROWS/128), 256>>>(hidden, wk, k, MROWS, NHKV*HD, HID);
    gemm_tf32<<<dim3((NHKV*HD)/128, MROWS/128), 256>>>(hidden, wv, v, MROWS, NHKV*HD, HID);
    norm_rope<<<(MROWS*NHQ *32 + 255) / 256, 256>>>(q, qw, NHQ,  ct, st);
    norm_rope<<<(MROWS*NHKV*32 + 255) / 256, 256>>>(k, kw, NHKV, ct, st);
    flash_tf32<<<dim3(SEQ/FBQ, NHQ, NB), 256, FLASH_BYTES>>>(q, k, v, attn);
    gemm_tf32<<<dim3(HID/128, MROWS/128), 256>>>(attn, wo, out, MROWS, HID, NHQ*HD);
}